// round 8
// baseline (speedup 1.0000x reference)
#include <cuda_runtime.h>
#include <cuda_fp16.h>
#include <cuda_bf16.h>

#define N_NODES 100000
#define N_EDGES 1000000
#define N_GRAPHS 512
#define HDIM 64
#define SCAN_B 1024
#define SCAN_NB ((N_NODES + SCAN_B - 1) / SCAN_B)   // 98

// ---------------- scratch (device globals; never passed from host) --------
// g_deg is self-cleaning: k_scan1 zeroes it after reading, so every call
// starts from zero (globals are zero-initialized at load).
__device__ __align__(16) float  g_dinv[N_NODES];
__device__ __align__(16) int    g_deg [N_NODES];
__device__ __align__(16) int    g_off [N_NODES + 1];
__device__ __align__(16) int    g_cur [N_NODES];
__device__ __align__(16) int    g_bsum[SCAN_NB];
__device__ __align__(16) int    g_csri[N_EDGES];          // src index only
__device__ __align__(16) float  g_xs  [N_NODES * 8];      // dinv[n]*x[n]
__device__ __align__(16) __half g_xwh [N_NODES * HDIM];   // dinv[n]*xw[n] (fp16)
__device__ __align__(16) float  g_agg [N_NODES * HDIM];   // fp32 preact
__device__ __align__(16) float  g_gmax[N_GRAPHS * HDIM];
__device__ __align__(16) float  g_gsum[N_GRAPHS * HDIM];
__device__ float g_gcnt[N_GRAPHS];

// ---------------- degree count (4 edges/thread) ---------------------------
__global__ void k_deg_count(const int* __restrict__ col) {
    int q = blockIdx.x * blockDim.x + threadIdx.x;
    if (q >= N_EDGES / 4) return;
    int4 c4 = ((const int4*)col)[q];
    atomicAdd(&g_deg[c4.x], 1);
    atomicAdd(&g_deg[c4.y], 1);
    atomicAdd(&g_deg[c4.z], 1);
    atomicAdd(&g_deg[c4.w], 1);
}

// ---------------- scan stage 1: per-chunk scan + dinv + deg self-zero -----
__global__ void k_scan1() {   // grid SCAN_NB, block 1024
    __shared__ int sh[SCAN_B];
    int idx = threadIdx.x;
    int n = blockIdx.x * SCAN_B + idx;
    int v = 0;
    if (n < N_NODES) {
        v = g_deg[n];
        g_deg[n] = 0;                          // clean for next call
        g_dinv[n] = rsqrtf((float)(v + 1));    // +1 self-loop
    }
    sh[idx] = v;
    __syncthreads();
#pragma unroll
    for (int d = 1; d < SCAN_B; d <<= 1) {
        int t = (idx >= d) ? sh[idx - d] : 0;
        __syncthreads();
        sh[idx] += t;
        __syncthreads();
    }
    if (n < N_NODES) g_off[n] = sh[idx] - v;          // exclusive (local)
    if (idx == SCAN_B - 1) g_bsum[blockIdx.x] = sh[idx];
}

// ---------------- scan stage 2: apply chunk prefixes + init g_cur +
// zero pooling buffers + pre-scale x rows (g_xs = dinv*x) ------------------
__global__ void k_scan3(const float* __restrict__ x) {
    __shared__ int sh[128];
    int t = threadIdx.x;
    int v = 0;
    if (t < 128) {
        v = (t < SCAN_NB) ? g_bsum[t] : 0;
        sh[t] = v;
    }
    __syncthreads();
#pragma unroll
    for (int d = 1; d < 128; d <<= 1) {
        int u = 0;
        if (t < 128 && t >= d) u = sh[t - d];
        __syncthreads();
        if (t < 128) sh[t] += u;
        __syncthreads();
    }
    if (t < 128) sh[t] -= v;   // exclusive chunk prefix
    __syncthreads();

    int n = blockIdx.x * 256 + t;
    if (n < N_NODES) {
        int o = g_off[n] + sh[n >> 10];
        g_off[n] = o;
        g_cur[n] = o;
        // pre-scale input row: g_xs[n] = dinv[n] * x[n]
        float dv = g_dinv[n];
        float4 a = ((const float4*)x)[(long)n * 2];
        float4 b = ((const float4*)x)[(long)n * 2 + 1];
        a.x *= dv; a.y *= dv; a.z *= dv; a.w *= dv;
        b.x *= dv; b.y *= dv; b.z *= dv; b.w *= dv;
        ((float4*)g_xs)[(long)n * 2]     = a;
        ((float4*)g_xs)[(long)n * 2 + 1] = b;
    }
    if (n == 0) g_off[N_NODES] = N_EDGES;
    // zero pooling buffers (consumed much later by k_pool)
    if (n < N_GRAPHS * HDIM) { g_gmax[n] = 0.0f; g_gsum[n] = 0.0f; }
    if (n < N_GRAPHS) g_gcnt[n] = 0.0f;
}

// ---------------- CSR fill: index only, 4 edges/thread --------------------
__global__ void k_fill(const int* __restrict__ rows, const int* __restrict__ cols) {
    int q = blockIdx.x * blockDim.x + threadIdx.x;
    if (q >= N_EDGES / 4) return;
    int4 r4 = ((const int4*)rows)[q];
    int4 c4 = ((const int4*)cols)[q];
    int s0 = atomicAdd(&g_cur[c4.x], 1);
    int s1 = atomicAdd(&g_cur[c4.y], 1);
    int s2 = atomicAdd(&g_cur[c4.z], 1);
    int s3 = atomicAdd(&g_cur[c4.w], 1);
    g_csri[s0] = r4.x;
    g_csri[s1] = r4.y;
    g_csri[s2] = r4.z;
    g_csri[s3] = r4.w;
}

// ---------------- layer 1 fused: g_agg = (A_hat @ x) @ W1 -----------------
// agg_x[n] = dinv[n] * (xs[n] + sum_r xs[r]);  preact1 = agg_x @ W1.
// Block 256 threads = 128 nodes; 2 thr/node.
__global__ void k_l1(const float* __restrict__ W1) {
    __shared__ __align__(16) float W1s[8 * 64];
    __shared__ __align__(16) float A[128 * 8];
    const int tid  = threadIdx.x;
    const int nloc = tid >> 1;
    const int half = tid & 1;
    const int n    = blockIdx.x * 128 + nloc;

    for (int i = tid; i < 512; i += 256) W1s[i] = W1[i];

    if (n < N_NODES) {
        const float4* xs4 = (const float4*)g_xs;
        int o0 = g_off[n], o1 = g_off[n + 1];
        float4 acc = xs4[(long)n * 2 + half];   // own scaled row
        int i = o0;
        for (; i + 2 <= o1; i += 2) {
            int r0 = g_csri[i], r1 = g_csri[i + 1];
            float4 v0 = xs4[(long)r0 * 2 + half];
            float4 v1 = xs4[(long)r1 * 2 + half];
            acc.x += v0.x + v1.x; acc.y += v0.y + v1.y;
            acc.z += v0.z + v1.z; acc.w += v0.w + v1.w;
        }
        if (i < o1) {
            float4 v0 = xs4[(long)g_csri[i] * 2 + half];
            acc.x += v0.x; acc.y += v0.y; acc.z += v0.z; acc.w += v0.w;
        }
        float dv = g_dinv[n];
        acc.x *= dv; acc.y *= dv; acc.z *= dv; acc.w *= dv;
        *(float4*)&A[nloc * 8 + half * 4] = acc;
    }
    __syncthreads();

    if (n < N_NODES) {
        float a[8];
        *(float4*)&a[0] = *(const float4*)&A[nloc * 8];
        *(float4*)&a[4] = *(const float4*)&A[nloc * 8 + 4];
        const int jc0 = half * 32;
        float4 acc[8];
#pragma unroll
        for (int g = 0; g < 8; g++) acc[g] = make_float4(0.f, 0.f, 0.f, 0.f);
#pragma unroll
        for (int k = 0; k < 8; k++) {
            float ak = a[k];
#pragma unroll
            for (int g = 0; g < 8; g++) {
                float4 w = *(const float4*)&W1s[k * 64 + jc0 + g * 4];
                acc[g].x = fmaf(ak, w.x, acc[g].x);
                acc[g].y = fmaf(ak, w.y, acc[g].y);
                acc[g].z = fmaf(ak, w.z, acc[g].z);
                acc[g].w = fmaf(ak, w.w, acc[g].w);
            }
        }
#pragma unroll
        for (int g = 0; g < 8; g++)
            *(float4*)&g_agg[(long)n * 64 + jc0 + g * 4] = acc[g];
    }
}

// ---------------- gather64: g_agg = dinv[c] * (y[c] + sum y[r]) -----------
// y rows are fp16 (already pre-scaled by dinv of their own node).
__global__ void k_gather64() {
    int gwid = (blockIdx.x * blockDim.x + threadIdx.x) >> 5;
    int lane = threadIdx.x & 31;
    if (gwid >= N_NODES) return;
    const __half2* __restrict__ xw2 = (const __half2*)g_xwh;
    int o0 = g_off[gwid], o1 = g_off[gwid + 1];
    float2 acc = __half22float2(xw2[(long)gwid * 32 + lane]);  // own y row
    int i = o0;
    for (; i + 4 <= o1; i += 4) {
        int r0 = g_csri[i], r1 = g_csri[i + 1], r2 = g_csri[i + 2], r3 = g_csri[i + 3];
        float2 v0 = __half22float2(xw2[(long)r0 * 32 + lane]);
        float2 v1 = __half22float2(xw2[(long)r1 * 32 + lane]);
        float2 v2 = __half22float2(xw2[(long)r2 * 32 + lane]);
        float2 v3 = __half22float2(xw2[(long)r3 * 32 + lane]);
        acc.x += v0.x + v1.x; acc.y += v0.y + v1.y;
        acc.x += v2.x + v3.x; acc.y += v2.y + v3.y;
    }
    for (; i < o1; i++) {
        float2 v0 = __half22float2(xw2[(long)g_csri[i] * 32 + lane]);
        acc.x += v0.x; acc.y += v0.y;
    }
    float dv = g_dinv[gwid];
    acc.x *= dv; acc.y *= dv;
    ((float2*)g_agg)[(long)gwid * 32 + lane] = acc;
}

// ---------------- GEMM K=64, reg-tiled 4x4:
// g_xwh[row] = dinv[row] * (relu(g_agg[row]+b) @ W)  in fp16 ---------------
__global__ __launch_bounds__(256) void k_gemmT(const float* __restrict__ W,
                                               const float* __restrict__ bias) {
    __shared__ __align__(16) float S[64 * 68];   // padded rows
    __shared__ __align__(16) float Wm[64 * 64];  // natural [k][j]
    __shared__ float Dv[64];
    const int tid  = threadIdx.x;
    const int base = blockIdx.x * 64;

    for (int i = tid; i < 1024; i += 256)
        ((float4*)Wm)[i] = ((const float4*)W)[i];
    if (tid < 64) {
        int row = base + tid;
        Dv[tid] = (row < N_NODES) ? g_dinv[row] : 0.0f;
    }
    for (int i = tid; i < 4096; i += 256) {
        int r = i >> 6, k = i & 63;
        int row = base + r;
        float v = (row < N_NODES) ? g_agg[(long)row * 64 + k] : 0.0f;
        S[r * 68 + k] = fmaxf(v + bias[k], 0.0f);
    }
    __syncthreads();

    const int tx = tid & 15;        // col group: j = tx*4..tx*4+3
    const int ty = tid >> 4;        // row group: r = ty*4..ty*4+3
    float4 acc0 = {0,0,0,0}, acc1 = {0,0,0,0}, acc2 = {0,0,0,0}, acc3 = {0,0,0,0};
    const float* Sr = &S[ty * 4 * 68];
    const int jc = tx << 2;

#pragma unroll
    for (int k4 = 0; k4 < 16; k4++) {
        const int kb = k4 * 4;
        float4 a0 = *(const float4*)&Sr[kb];
        float4 a1 = *(const float4*)&Sr[68 + kb];
        float4 a2 = *(const float4*)&Sr[136 + kb];
        float4 a3 = *(const float4*)&Sr[204 + kb];
        float4 w0 = *(const float4*)&Wm[(kb + 0) * 64 + jc];
        float4 w1 = *(const float4*)&Wm[(kb + 1) * 64 + jc];
        float4 w2 = *(const float4*)&Wm[(kb + 2) * 64 + jc];
        float4 w3 = *(const float4*)&Wm[(kb + 3) * 64 + jc];

        acc0.x = fmaf(a0.x, w0.x, acc0.x); acc0.y = fmaf(a0.x, w0.y, acc0.y);
        acc0.z = fmaf(a0.x, w0.z, acc0.z); acc0.w = fmaf(a0.x, w0.w, acc0.w);
        acc0.x = fmaf(a0.y, w1.x, acc0.x); acc0.y = fmaf(a0.y, w1.y, acc0.y);
        acc0.z = fmaf(a0.y, w1.z, acc0.z); acc0.w = fmaf(a0.y, w1.w, acc0.w);
        acc0.x = fmaf(a0.z, w2.x, acc0.x); acc0.y = fmaf(a0.z, w2.y, acc0.y);
        acc0.z = fmaf(a0.z, w2.z, acc0.z); acc0.w = fmaf(a0.z, w2.w, acc0.w);
        acc0.x = fmaf(a0.w, w3.x, acc0.x); acc0.y = fmaf(a0.w, w3.y, acc0.y);
        acc0.z = fmaf(a0.w, w3.z, acc0.z); acc0.w = fmaf(a0.w, w3.w, acc0.w);

        acc1.x = fmaf(a1.x, w0.x, acc1.x); acc1.y = fmaf(a1.x, w0.y, acc1.y);
        acc1.z = fmaf(a1.x, w0.z, acc1.z); acc1.w = fmaf(a1.x, w0.w, acc1.w);
        acc1.x = fmaf(a1.y, w1.x, acc1.x); acc1.y = fmaf(a1.y, w1.y, acc1.y);
        acc1.z = fmaf(a1.y, w1.z, acc1.z); acc1.w = fmaf(a1.y, w1.w, acc1.w);
        acc1.x = fmaf(a1.z, w2.x, acc1.x); acc1.y = fmaf(a1.z, w2.y, acc1.y);
        acc1.z = fmaf(a1.z, w2.z, acc1.z); acc1.w = fmaf(a1.z, w2.w, acc1.w);
        acc1.x = fmaf(a1.w, w3.x, acc1.x); acc1.y = fmaf(a1.w, w3.y, acc1.y);
        acc1.z = fmaf(a1.w, w3.z, acc1.z); acc1.w = fmaf(a1.w, w3.w, acc1.w);

        acc2.x = fmaf(a2.x, w0.x, acc2.x); acc2.y = fmaf(a2.x, w0.y, acc2.y);
        acc2.z = fmaf(a2.x, w0.z, acc2.z); acc2.w = fmaf(a2.x, w0.w, acc2.w);
        acc2.x = fmaf(a2.y, w1.x, acc2.x); acc2.y = fmaf(a2.y, w1.y, acc2.y);
        acc2.z = fmaf(a2.y, w1.z, acc2.z); acc2.w = fmaf(a2.y, w1.w, acc2.w);
        acc2.x = fmaf(a2.z, w2.x, acc2.x); acc2.y = fmaf(a2.z, w2.y, acc2.y);
        acc2.z = fmaf(a2.z, w2.z, acc2.z); acc2.w = fmaf(a2.z, w2.w, acc2.w);
        acc2.x = fmaf(a2.w, w3.x, acc2.x); acc2.y = fmaf(a2.w, w3.y, acc2.y);
        acc2.z = fmaf(a2.w, w3.z, acc2.z); acc2.w = fmaf(a2.w, w3.w, acc2.w);

        acc3.x = fmaf(a3.x, w0.x, acc3.x); acc3.y = fmaf(a3.x, w0.y, acc3.y);
        acc3.z = fmaf(a3.x, w0.z, acc3.z); acc3.w = fmaf(a3.x, w0.w, acc3.w);
        acc3.x = fmaf(a3.y, w1.x, acc3.x); acc3.y = fmaf(a3.y, w1.y, acc3.y);
        acc3.z = fmaf(a3.y, w1.z, acc3.z); acc3.w = fmaf(a3.y, w1.w, acc3.w);
        acc3.x = fmaf(a3.z, w2.x, acc3.x); acc3.y = fmaf(a3.z, w2.y, acc3.y);
        acc3.z = fmaf(a3.z, w2.z, acc3.z); acc3.w = fmaf(a3.z, w2.w, acc3.w);
        acc3.x = fmaf(a3.w, w3.x, acc3.x); acc3.y = fmaf(a3.w, w3.y, acc3.y);
        acc3.z = fmaf(a3.w, w3.z, acc3.z); acc3.w = fmaf(a3.w, w3.w, acc3.w);
    }

    const int r0 = base + ty * 4;
#pragma unroll
    for (int m = 0; m < 4; m++) {
        float4 a = (m == 0) ? acc0 : (m == 1) ? acc1 : (m == 2) ? acc2 : acc3;
        int row = r0 + m;
        if (row < N_NODES) {
            float dv = Dv[ty * 4 + m];
            __half2 pair[2];
            pair[0] = __floats2half2_rn(a.x * dv, a.y * dv);
            pair[1] = __floats2half2_rn(a.z * dv, a.w * dv);
            *(uint2*)&g_xwh[(long)row * 64 + jc] = *(uint2*)pair;  // 8B store
        }
    }
}

// ---------------- pooling (sorted batch, run-length flush) ----------------
__global__ void k_pool(const float* __restrict__ b4, const int* __restrict__ batch) {
    int j = threadIdx.x & 63;
    int y = threadIdx.x >> 6;
    int start = blockIdx.x * 512 + y * 128;
    int end   = min(start + 128, N_NODES);
    if (start >= end) return;

    float bj = b4[j];
    int   curg = batch[start];
    float mx = 0.f, sm = 0.f;
    int   cnt = 0;

    for (int n = start; n < end; n++) {
        int g = batch[n];
        if (g != curg) {
            atomicMax((int*)&g_gmax[curg * 64 + j], __float_as_int(mx));
            atomicAdd(&g_gsum[curg * 64 + j], sm);
            if (j == 0) atomicAdd(&g_gcnt[curg], (float)cnt);
            curg = g; mx = 0.f; sm = 0.f; cnt = 0;
        }
        float v = fmaxf(g_agg[(long)n * 64 + j] + bj, 0.0f);
        mx = fmaxf(mx, v);
        sm += v;
        cnt++;
    }
    atomicMax((int*)&g_gmax[curg * 64 + j], __float_as_int(mx));
    atomicAdd(&g_gsum[curg * 64 + j], sm);
    if (j == 0) atomicAdd(&g_gcnt[curg], (float)cnt);
}

// ---------------- head ----------------------------------------------------
__global__ void k_head(const float* __restrict__ Wo, const float* __restrict__ bo,
                       float* __restrict__ out, int write_hg) {
    int g = blockIdx.x;
    int j = threadIdx.x;  // 0..127
    float cnt = fmaxf(g_gcnt[g], 1.0f);
    float val = (j < 64) ? g_gmax[g * 64 + j] : g_gsum[g * 64 + (j - 64)] / cnt;
    if (write_hg) out[N_GRAPHS + (long)g * 128 + j] = val;

    float p = val * Wo[j];
#pragma unroll
    for (int off = 16; off > 0; off >>= 1)
        p += __shfl_down_sync(0xffffffff, p, off);

    __shared__ float red[4];
    if ((j & 31) == 0) red[j >> 5] = p;
    __syncthreads();
    if (j == 0) out[g] = red[0] + red[1] + red[2] + red[3] + bo[0];
}

// ---------------- launch ---------------------------------------------------
extern "C" void kernel_launch(void* const* d_in, const int* in_sizes, int n_in,
                              void* d_out, int out_size) {
    const float* x     = (const float*)d_in[0];
    const int*   ei    = (const int*)  d_in[1];   // [2, E]
    const int*   batch = (const int*)  d_in[2];
    const float* W1 = (const float*)d_in[3];  const float* b1 = (const float*)d_in[4];
    const float* W2 = (const float*)d_in[5];  const float* b2 = (const float*)d_in[6];
    const float* W3 = (const float*)d_in[7];  const float* b3 = (const float*)d_in[8];
    const float* W4 = (const float*)d_in[9];  const float* b4 = (const float*)d_in[10];
    const float* Wo = (const float*)d_in[11]; const float* bo = (const float*)d_in[12];

    const int* rows = ei;            // source
    const int* cols = ei + N_EDGES;  // target

    float* out = (float*)d_out;
    int write_hg = (out_size >= N_GRAPHS + N_GRAPHS * 2 * HDIM) ? 1 : 0;

    const int NB_N  = (N_NODES + 255) / 256;
    const int NB_E4 = (N_EDGES / 4 + 255) / 256;

    // CSR build (g_deg arrives zeroed from previous call / load-time init)
    k_deg_count<<<NB_E4, 256>>>(cols);
    k_scan1    <<<SCAN_NB, SCAN_B>>>();
    k_scan3    <<<NB_N, 256>>>(x);
    k_fill     <<<NB_E4, 256>>>(rows, cols);

    const int L1_BLKS  = (N_NODES + 127) / 128;          // 782
    const int GT_BLKS  = (N_NODES + 63) / 64;            // 1563
    const int G64_BLKS = (N_NODES * 32 + 255) / 256;     // 12500

    // layer 1: fused 8-dim gather + GEMM -> g_agg = preact1 (fp32)
    k_l1<<<L1_BLKS, 256>>>(W1);
    // layers 2..4: g_xwh = dinv*relu(g_agg+b) @ W (fp16), then aggregate
    k_gemmT<<<GT_BLKS, 256>>>(W2, b1);
    k_gather64<<<G64_BLKS, 256>>>();               // g_agg = preact2
    k_gemmT<<<GT_BLKS, 256>>>(W3, b2);
    k_gather64<<<G64_BLKS, 256>>>();               // preact3
    k_gemmT<<<GT_BLKS, 256>>>(W4, b3);
    k_gather64<<<G64_BLKS, 256>>>();               // preact4

    // pooling + head (relu(+b4) fused in pool)
    k_pool<<<(N_NODES + 511) / 512, 256>>>(b4, batch);
    k_head<<<N_GRAPHS, 128>>>(Wo, bo, out, write_hg);
}

// round 11
// speedup vs baseline: 1.4527x; 1.4527x over previous
#include <cuda_runtime.h>
#include <cuda_fp16.h>
#include <cuda_bf16.h>
#include <cstdint>

#define N_NODES 100000
#define N_EDGES 1000000
#define N_GRAPHS 512
#define HDIM 64
#define SCAN_B 1024
#define SCAN_NB ((N_NODES + SCAN_B - 1) / SCAN_B)   // 98

// ---------------- scratch (device globals; never passed from host) --------
__device__ __align__(16) float  g_dinv[N_NODES];
__device__ __align__(16) int    g_deg [N_NODES];
__device__ __align__(16) int    g_off [N_NODES + 1];
__device__ __align__(16) int    g_cur [N_NODES];
__device__ __align__(16) int    g_bsum[SCAN_NB];
__device__ __align__(16) int    g_csri[N_EDGES];          // src index only
__device__ __align__(16) float  g_xs  [N_NODES * 8];      // dinv[n]*x[n]
__device__ __align__(16) __half g_xwh [N_NODES * HDIM];   // dinv[n]*xw[n] (fp16)
__device__ __align__(16) float  g_agg [N_NODES * HDIM];   // fp32 preact
__device__ __align__(16) float  g_gmax[N_GRAPHS * HDIM];
__device__ __align__(16) float  g_gsum[N_GRAPHS * HDIM];
__device__ float g_gcnt[N_GRAPHS];

__device__ __forceinline__ uint32_t smem_u32(const void* p) {
    return (uint32_t)__cvta_generic_to_shared(p);
}

// ---------------- degree count (4 edges/thread) ---------------------------
__global__ void k_deg_count(const int* __restrict__ col) {
    int q = blockIdx.x * blockDim.x + threadIdx.x;
    if (q >= N_EDGES / 4) return;
    int4 c4 = ((const int4*)col)[q];
    atomicAdd(&g_deg[c4.x], 1);
    atomicAdd(&g_deg[c4.y], 1);
    atomicAdd(&g_deg[c4.z], 1);
    atomicAdd(&g_deg[c4.w], 1);
}

// ---------------- scan stage 1: per-chunk scan + dinv + deg self-zero -----
__global__ void k_scan1() {   // grid SCAN_NB, block 1024
    __shared__ int sh[SCAN_B];
    int idx = threadIdx.x;
    int n = blockIdx.x * SCAN_B + idx;
    int v = 0;
    if (n < N_NODES) {
        v = g_deg[n];
        g_deg[n] = 0;                          // clean for next call
        g_dinv[n] = rsqrtf((float)(v + 1));    // +1 self-loop
    }
    sh[idx] = v;
    __syncthreads();
#pragma unroll
    for (int d = 1; d < SCAN_B; d <<= 1) {
        int t = (idx >= d) ? sh[idx - d] : 0;
        __syncthreads();
        sh[idx] += t;
        __syncthreads();
    }
    if (n < N_NODES) g_off[n] = sh[idx] - v;          // exclusive (local)
    if (idx == SCAN_B - 1) g_bsum[blockIdx.x] = sh[idx];
}

// ---------------- scan stage 2: apply chunk prefixes + init g_cur +
// zero pooling buffers + pre-scale x rows (g_xs = dinv*x) ------------------
__global__ void k_scan3(const float* __restrict__ x) {
    __shared__ int sh[128];
    int t = threadIdx.x;
    int v = 0;
    if (t < 128) {
        v = (t < SCAN_NB) ? g_bsum[t] : 0;
        sh[t] = v;
    }
    __syncthreads();
#pragma unroll
    for (int d = 1; d < 128; d <<= 1) {
        int u = 0;
        if (t < 128 && t >= d) u = sh[t - d];
        __syncthreads();
        if (t < 128) sh[t] += u;
        __syncthreads();
    }
    if (t < 128) sh[t] -= v;   // exclusive chunk prefix
    __syncthreads();

    int n = blockIdx.x * 256 + t;
    if (n < N_NODES) {
        int o = g_off[n] + sh[n >> 10];
        g_off[n] = o;
        g_cur[n] = o;
        float dv = g_dinv[n];
        float4 a = ((const float4*)x)[(long)n * 2];
        float4 b = ((const float4*)x)[(long)n * 2 + 1];
        a.x *= dv; a.y *= dv; a.z *= dv; a.w *= dv;
        b.x *= dv; b.y *= dv; b.z *= dv; b.w *= dv;
        ((float4*)g_xs)[(long)n * 2]     = a;
        ((float4*)g_xs)[(long)n * 2 + 1] = b;
    }
    if (n == 0) g_off[N_NODES] = N_EDGES;
    if (n < N_GRAPHS * HDIM) { g_gmax[n] = 0.0f; g_gsum[n] = 0.0f; }
    if (n < N_GRAPHS) g_gcnt[n] = 0.0f;
}

// ---------------- CSR fill: index only, 4 edges/thread --------------------
__global__ void k_fill(const int* __restrict__ rows, const int* __restrict__ cols) {
    int q = blockIdx.x * blockDim.x + threadIdx.x;
    if (q >= N_EDGES / 4) return;
    int4 r4 = ((const int4*)rows)[q];
    int4 c4 = ((const int4*)cols)[q];
    int s0 = atomicAdd(&g_cur[c4.x], 1);
    int s1 = atomicAdd(&g_cur[c4.y], 1);
    int s2 = atomicAdd(&g_cur[c4.z], 1);
    int s3 = atomicAdd(&g_cur[c4.w], 1);
    g_csri[s0] = r4.x;
    g_csri[s1] = r4.y;
    g_csri[s2] = r4.z;
    g_csri[s3] = r4.w;
}

// ---------------- layer 1 fused: g_agg = (A_hat @ x) @ W1 -----------------
__global__ void k_l1(const float* __restrict__ W1) {
    __shared__ __align__(16) float W1s[8 * 64];
    __shared__ __align__(16) float A[128 * 8];
    const int tid  = threadIdx.x;
    const int nloc = tid >> 1;
    const int half = tid & 1;
    const int n    = blockIdx.x * 128 + nloc;

    for (int i = tid; i < 512; i += 256) W1s[i] = W1[i];

    if (n < N_NODES) {
        const float4* xs4 = (const float4*)g_xs;
        int o0 = g_off[n], o1 = g_off[n + 1];
        float4 acc = xs4[(long)n * 2 + half];   // own scaled row
        int i = o0;
        for (; i + 2 <= o1; i += 2) {
            int r0 = g_csri[i], r1 = g_csri[i + 1];
            float4 v0 = xs4[(long)r0 * 2 + half];
            float4 v1 = xs4[(long)r1 * 2 + half];
            acc.x += v0.x + v1.x; acc.y += v0.y + v1.y;
            acc.z += v0.z + v1.z; acc.w += v0.w + v1.w;
        }
        if (i < o1) {
            float4 v0 = xs4[(long)g_csri[i] * 2 + half];
            acc.x += v0.x; acc.y += v0.y; acc.z += v0.z; acc.w += v0.w;
        }
        float dv = g_dinv[n];
        acc.x *= dv; acc.y *= dv; acc.z *= dv; acc.w *= dv;
        *(float4*)&A[nloc * 8 + half * 4] = acc;
    }
    __syncthreads();

    if (n < N_NODES) {
        float a[8];
        *(float4*)&a[0] = *(const float4*)&A[nloc * 8];
        *(float4*)&a[4] = *(const float4*)&A[nloc * 8 + 4];
        const int jc0 = half * 32;
        float4 acc[8];
#pragma unroll
        for (int g = 0; g < 8; g++) acc[g] = make_float4(0.f, 0.f, 0.f, 0.f);
#pragma unroll
        for (int k = 0; k < 8; k++) {
            float ak = a[k];
#pragma unroll
            for (int g = 0; g < 8; g++) {
                float4 w = *(const float4*)&W1s[k * 64 + jc0 + g * 4];
                acc[g].x = fmaf(ak, w.x, acc[g].x);
                acc[g].y = fmaf(ak, w.y, acc[g].y);
                acc[g].z = fmaf(ak, w.z, acc[g].z);
                acc[g].w = fmaf(ak, w.w, acc[g].w);
            }
        }
#pragma unroll
        for (int g = 0; g < 8; g++)
            *(float4*)&g_agg[(long)n * 64 + jc0 + g * 4] = acc[g];
    }
}

// ---------------- gather64: g_agg = dinv[c] * (y[c] + sum y[r]) -----------
__global__ void k_gather64() {
    int gwid = (blockIdx.x * blockDim.x + threadIdx.x) >> 5;
    int lane = threadIdx.x & 31;
    if (gwid >= N_NODES) return;
    const __half2* __restrict__ xw2 = (const __half2*)g_xwh;
    int o0 = g_off[gwid], o1 = g_off[gwid + 1];
    float2 acc = __half22float2(xw2[(long)gwid * 32 + lane]);  // own y row
    int i = o0;
    for (; i + 4 <= o1; i += 4) {
        int r0 = g_csri[i], r1 = g_csri[i + 1], r2 = g_csri[i + 2], r3 = g_csri[i + 3];
        float2 v0 = __half22float2(xw2[(long)r0 * 32 + lane]);
        float2 v1 = __half22float2(xw2[(long)r1 * 32 + lane]);
        float2 v2 = __half22float2(xw2[(long)r2 * 32 + lane]);
        float2 v3 = __half22float2(xw2[(long)r3 * 32 + lane]);
        acc.x += v0.x + v1.x; acc.y += v0.y + v1.y;
        acc.x += v2.x + v3.x; acc.y += v2.y + v3.y;
    }
    for (; i < o1; i++) {
        float2 v0 = __half22float2(xw2[(long)g_csri[i] * 32 + lane]);
        acc.x += v0.x; acc.y += v0.y;
    }
    float dv = g_dinv[gwid];
    acc.x *= dv; acc.y *= dv;
    ((float2*)g_agg)[(long)gwid * 32 + lane] = acc;
}

// ---------------- GEMM K=64 via tensor cores (mma.m16n8k16 f16->f32) ------
// g_xwh[row] = dinv[row] * (relu(g_agg[row]+b) @ W), fp16 out.
// Block 256 thr = 8 warps; warp (wm,wn) = (w>>1, w&1) computes m16 x n32.
// Smem rows padded to 72 halves (144B) -> conflict-free ldmatrix.
__global__ __launch_bounds__(256) void k_gemmT(const float* __restrict__ W,
                                               const float* __restrict__ bias) {
    __shared__ __align__(16) __half Sh[64 * 72];  // A fp16
    __shared__ __align__(16) __half Wh[64 * 72];  // W fp16
    __shared__ float Dv[64];
    const int tid  = threadIdx.x;
    const int base = blockIdx.x * 64;

    if (tid < 64) {
        int row = base + tid;
        Dv[tid] = (row < N_NODES) ? g_dinv[row] : 0.0f;
    }
    // stage A = relu(agg + bias) -> fp16
    for (int i = tid; i < 2048; i += 256) {
        int r = i >> 5, k2 = i & 31;        // k2 = half2 index (2 cols)
        int row = base + r;
        float2 v = make_float2(0.f, 0.f);
        if (row < N_NODES) v = *(const float2*)&g_agg[(long)row * 64 + k2 * 2];
        float2 bb = *(const float2*)&bias[k2 * 2];
        ((__half2*)Sh)[r * 36 + k2] =
            __floats2half2_rn(fmaxf(v.x + bb.x, 0.f), fmaxf(v.y + bb.y, 0.f));
    }
    // stage W -> fp16
    for (int i = tid; i < 2048; i += 256) {
        int k = i >> 5, j2 = i & 31;
        float2 w = *(const float2*)&W[k * 64 + j2 * 2];
        ((__half2*)Wh)[k * 36 + j2] = __floats2half2_rn(w.x, w.y);
    }
    __syncthreads();

    const int warp = tid >> 5, lane = tid & 31;
    const int m_base = (warp >> 1) * 16;
    const int n_base = (warp & 1) * 32;
    const int lt   = lane & 7;
    const int tile = lane >> 3;

    float d[4][4];
#pragma unroll
    for (int nt = 0; nt < 4; nt++)
#pragma unroll
        for (int q = 0; q < 4; q++) d[nt][q] = 0.f;

#pragma unroll
    for (int kc = 0; kc < 4; kc++) {
        // A fragment: tiles [m0k0][m8k0][m0k8][m8k8]
        int arow = m_base + lt + ((tile & 1) ? 8 : 0);
        int acol = kc * 16 + ((tile & 2) ? 8 : 0);
        uint32_t a0, a1, a2, a3;
        {
            uint32_t addr = smem_u32(&Sh[arow * 72 + acol]);
            asm volatile("ldmatrix.sync.aligned.m8n8.x4.shared.b16 {%0,%1,%2,%3}, [%4];"
                         : "=r"(a0), "=r"(a1), "=r"(a2), "=r"(a3) : "r"(addr));
        }
#pragma unroll
        for (int g = 0; g < 2; g++) {
            // B fragments (trans): tiles [k0,n0][k8,n0][k0,n8][k8,n8]
            int krow = kc * 16 + lt + ((tile & 1) ? 8 : 0);
            int bcol = n_base + g * 16 + ((tile & 2) ? 8 : 0);
            uint32_t b0, b1, b2, b3;
            uint32_t addr = smem_u32(&Wh[krow * 72 + bcol]);
            asm volatile("ldmatrix.sync.aligned.m8n8.x4.trans.shared.b16 {%0,%1,%2,%3}, [%4];"
                         : "=r"(b0), "=r"(b1), "=r"(b2), "=r"(b3) : "r"(addr));
            asm volatile("mma.sync.aligned.m16n8k16.row.col.f32.f16.f16.f32 "
                         "{%0,%1,%2,%3},{%4,%5,%6,%7},{%8,%9},{%0,%1,%2,%3};"
                         : "+f"(d[g*2][0]), "+f"(d[g*2][1]), "+f"(d[g*2][2]), "+f"(d[g*2][3])
                         : "r"(a0), "r"(a1), "r"(a2), "r"(a3), "r"(b0), "r"(b1));
            asm volatile("mma.sync.aligned.m16n8k16.row.col.f32.f16.f16.f32 "
                         "{%0,%1,%2,%3},{%4,%5,%6,%7},{%8,%9},{%0,%1,%2,%3};"
                         : "+f"(d[g*2+1][0]), "+f"(d[g*2+1][1]), "+f"(d[g*2+1][2]), "+f"(d[g*2+1][3])
                         : "r"(a0), "r"(a1), "r"(a2), "r"(a3), "r"(b2), "r"(b3));
        }
    }

    // epilogue: scale by dinv, fp16 store
    const int group = lane >> 2, t4 = lane & 3;
    const int r0g = base + m_base + group;
    const int r1g = r0g + 8;
    const float dv0 = Dv[m_base + group];
    const float dv1 = Dv[m_base + group + 8];
#pragma unroll
    for (int nt = 0; nt < 4; nt++) {
        int ncol = n_base + nt * 8 + t4 * 2;
        if (r0g < N_NODES)
            *(__half2*)&g_xwh[(long)r0g * 64 + ncol] =
                __floats2half2_rn(d[nt][0] * dv0, d[nt][1] * dv0);
        if (r1g < N_NODES)
            *(__half2*)&g_xwh[(long)r1g * 64 + ncol] =
                __floats2half2_rn(d[nt][2] * dv1, d[nt][3] * dv1);
    }
}

// ---------------- pooling (sorted batch, run-length flush, 32-node chunks)
__global__ void k_pool(const float* __restrict__ b4, const int* __restrict__ batch) {
    int j = threadIdx.x & 63;
    int y = threadIdx.x >> 6;
    int start = blockIdx.x * 128 + y * 32;
    int end   = min(start + 32, N_NODES);
    if (start >= end) return;

    float bj = b4[j];
    int   curg = batch[start];
    float mx = 0.f, sm = 0.f;
    int   cnt = 0;

    for (int n = start; n < end; n++) {
        int g = batch[n];
        if (g != curg) {
            atomicMax((int*)&g_gmax[curg * 64 + j], __float_as_int(mx));
            atomicAdd(&g_gsum[curg * 64 + j], sm);
            if (j == 0) atomicAdd(&g_gcnt[curg], (float)cnt);
            curg = g; mx = 0.f; sm = 0.f; cnt = 0;
        }
        float v = fmaxf(g_agg[(long)n * 64 + j] + bj, 0.0f);
        mx = fmaxf(mx, v);
        sm += v;
        cnt++;
    }
    atomicMax((int*)&g_gmax[curg * 64 + j], __float_as_int(mx));
    atomicAdd(&g_gsum[curg * 64 + j], sm);
    if (j == 0) atomicAdd(&g_gcnt[curg], (float)cnt);
}

// ---------------- head ----------------------------------------------------
__global__ void k_head(const float* __restrict__ Wo, const float* __restrict__ bo,
                       float* __restrict__ out, int write_hg) {
    int g = blockIdx.x;
    int j = threadIdx.x;  // 0..127
    float cnt = fmaxf(g_gcnt[g], 1.0f);
    float val = (j < 64) ? g_gmax[g * 64 + j] : g_gsum[g * 64 + (j - 64)] / cnt;
    if (write_hg) out[N_GRAPHS + (long)g * 128 + j] = val;

    float p = val * Wo[j];
#pragma unroll
    for (int off = 16; off > 0; off >>= 1)
        p += __shfl_down_sync(0xffffffff, p, off);

    __shared__ float red[4];
    if ((j & 31) == 0) red[j >> 5] = p;
    __syncthreads();
    if (j == 0) out[g] = red[0] + red[1] + red[2] + red[3] + bo[0];
}

// ---------------- launch ---------------------------------------------------
extern "C" void kernel_launch(void* const* d_in, const int* in_sizes, int n_in,
                              void* d_out, int out_size) {
    const float* x     = (const float*)d_in[0];
    const int*   ei    = (const int*)  d_in[1];   // [2, E]
    const int*   batch = (const int*)  d_in[2];
    const float* W1 = (const float*)d_in[3];  const float* b1 = (const float*)d_in[4];
    const float* W2 = (const float*)d_in[5];  const float* b2 = (const float*)d_in[6];
    const float* W3 = (const float*)d_in[7];  const float* b3 = (const float*)d_in[8];
    const float* W4 = (const float*)d_in[9];  const float* b4 = (const float*)d_in[10];
    const float* Wo = (const float*)d_in[11]; const float* bo = (const float*)d_in[12];

    const int* rows = ei;            // source
    const int* cols = ei + N_EDGES;  // target

    float* out = (float*)d_out;
    int write_hg = (out_size >= N_GRAPHS + N_GRAPHS * 2 * HDIM) ? 1 : 0;

    const int NB_N  = (N_NODES + 255) / 256;
    const int NB_E4 = (N_EDGES / 4 + 255) / 256;

    // CSR build (g_deg arrives zeroed from previous call / load-time init)
    k_deg_count<<<NB_E4, 256>>>(cols);
    k_scan1    <<<SCAN_NB, SCAN_B>>>();
    k_scan3    <<<NB_N, 256>>>(x);
    k_fill     <<<NB_E4, 256>>>(rows, cols);

    const int L1_BLKS  = (N_NODES + 127) / 128;          // 782
    const int GT_BLKS  = (N_NODES + 63) / 64;            // 1563
    const int G64_BLKS = (N_NODES * 32 + 255) / 256;     // 12500

    // layer 1: fused 8-dim gather + GEMM -> g_agg = preact1 (fp32)
    k_l1<<<L1_BLKS, 256>>>(W1);
    // layers 2..4: g_xwh = dinv*relu(g_agg+b) @ W (fp16, tensor cores), gather
    k_gemmT<<<GT_BLKS, 256>>>(W2, b1);
    k_gather64<<<G64_BLKS, 256>>>();               // g_agg = preact2
    k_gemmT<<<GT_BLKS, 256>>>(W3, b2);
    k_gather64<<<G64_BLKS, 256>>>();               // preact3
    k_gemmT<<<GT_BLKS, 256>>>(W4, b3);
    k_gather64<<<G64_BLKS, 256>>>();               // preact4

    // pooling + head (relu(+b4) fused in pool)
    k_pool<<<(N_NODES + 127) / 128, 256>>>(b4, batch);
    k_head<<<N_GRAPHS, 128>>>(Wo, bo, out, write_hg);
}

// round 12
// speedup vs baseline: 1.4530x; 1.0002x over previous
#include <cuda_runtime.h>
#include <cuda_fp16.h>
#include <cuda_bf16.h>
#include <cstdint>

#define N_NODES 100000
#define N_EDGES 1000000
#define N_GRAPHS 512
#define HDIM 64
#define SCAN_B 1024
#define SCAN_NB ((N_NODES + SCAN_B - 1) / SCAN_B)   // 98

// ---------------- scratch (device globals; never passed from host) --------
__device__ __align__(16) float  g_dinv[N_NODES];
__device__ __align__(16) int    g_deg [N_NODES];
__device__ __align__(16) int    g_off [N_NODES + 1];
__device__ __align__(16) int    g_cur [N_NODES];
__device__ __align__(16) int    g_bsum[SCAN_NB];
__device__ __align__(16) int    g_csri[N_EDGES];          // src index only
__device__ __align__(16) float  g_xs  [N_NODES * 8];      // dinv[n]*x[n]
__device__ __align__(16) __half g_xwh [N_NODES * HDIM];   // y = dinv*xw (fp16)
__device__ __align__(16) __half g_aggh[N_NODES * HDIM];   // h = relu(preact+b) fp16
__device__ __align__(16) float  g_agg [N_NODES * HDIM];   // fp32 preact4 (for pool)
__device__ __align__(16) float  g_gmax[N_GRAPHS * HDIM];
__device__ __align__(16) float  g_gsum[N_GRAPHS * HDIM];
__device__ float g_gcnt[N_GRAPHS];

__device__ __forceinline__ uint32_t smem_u32(const void* p) {
    return (uint32_t)__cvta_generic_to_shared(p);
}

// ---------------- degree count (8 edges/thread) ---------------------------
__global__ void k_deg_count(const int* __restrict__ col) {
    int q = blockIdx.x * blockDim.x + threadIdx.x;
    if (q >= N_EDGES / 8) return;
    int4 a = ((const int4*)col)[q * 2];
    int4 b = ((const int4*)col)[q * 2 + 1];
    atomicAdd(&g_deg[a.x], 1); atomicAdd(&g_deg[a.y], 1);
    atomicAdd(&g_deg[a.z], 1); atomicAdd(&g_deg[a.w], 1);
    atomicAdd(&g_deg[b.x], 1); atomicAdd(&g_deg[b.y], 1);
    atomicAdd(&g_deg[b.z], 1); atomicAdd(&g_deg[b.w], 1);
}

// ---------------- scan stage 1: per-chunk scan + dinv + deg self-zero -----
__global__ void k_scan1() {   // grid SCAN_NB, block 1024
    __shared__ int sh[SCAN_B];
    int idx = threadIdx.x;
    int n = blockIdx.x * SCAN_B + idx;
    int v = 0;
    if (n < N_NODES) {
        v = g_deg[n];
        g_deg[n] = 0;                          // clean for next call
        g_dinv[n] = rsqrtf((float)(v + 1));    // +1 self-loop
    }
    sh[idx] = v;
    __syncthreads();
#pragma unroll
    for (int d = 1; d < SCAN_B; d <<= 1) {
        int t = (idx >= d) ? sh[idx - d] : 0;
        __syncthreads();
        sh[idx] += t;
        __syncthreads();
    }
    if (n < N_NODES) g_off[n] = sh[idx] - v;          // exclusive (local)
    if (idx == SCAN_B - 1) g_bsum[blockIdx.x] = sh[idx];
}

// ---------------- scan stage 2: apply chunk prefixes + init g_cur +
// zero pooling buffers + pre-scale x rows (g_xs = dinv*x) ------------------
__global__ void k_scan3(const float* __restrict__ x) {
    __shared__ int sh[128];
    int t = threadIdx.x;
    int v = 0;
    if (t < 128) {
        v = (t < SCAN_NB) ? g_bsum[t] : 0;
        sh[t] = v;
    }
    __syncthreads();
#pragma unroll
    for (int d = 1; d < 128; d <<= 1) {
        int u = 0;
        if (t < 128 && t >= d) u = sh[t - d];
        __syncthreads();
        if (t < 128) sh[t] += u;
        __syncthreads();
    }
    if (t < 128) sh[t] -= v;   // exclusive chunk prefix
    __syncthreads();

    int n = blockIdx.x * 256 + t;
    if (n < N_NODES) {
        int o = g_off[n] + sh[n >> 10];
        g_off[n] = o;
        g_cur[n] = o;
        float dv = g_dinv[n];
        float4 a = ((const float4*)x)[(long)n * 2];
        float4 b = ((const float4*)x)[(long)n * 2 + 1];
        a.x *= dv; a.y *= dv; a.z *= dv; a.w *= dv;
        b.x *= dv; b.y *= dv; b.z *= dv; b.w *= dv;
        ((float4*)g_xs)[(long)n * 2]     = a;
        ((float4*)g_xs)[(long)n * 2 + 1] = b;
    }
    if (n == 0) g_off[N_NODES] = N_EDGES;
    if (n < N_GRAPHS * HDIM) { g_gmax[n] = 0.0f; g_gsum[n] = 0.0f; }
    if (n < N_GRAPHS) g_gcnt[n] = 0.0f;
}

// ---------------- CSR fill: index only, 8 edges/thread --------------------
__global__ void k_fill(const int* __restrict__ rows, const int* __restrict__ cols) {
    int q = blockIdx.x * blockDim.x + threadIdx.x;
    if (q >= N_EDGES / 8) return;
    int4 ra = ((const int4*)rows)[q * 2];
    int4 rb = ((const int4*)rows)[q * 2 + 1];
    int4 ca = ((const int4*)cols)[q * 2];
    int4 cb = ((const int4*)cols)[q * 2 + 1];
    int s0 = atomicAdd(&g_cur[ca.x], 1);
    int s1 = atomicAdd(&g_cur[ca.y], 1);
    int s2 = atomicAdd(&g_cur[ca.z], 1);
    int s3 = atomicAdd(&g_cur[ca.w], 1);
    int s4 = atomicAdd(&g_cur[cb.x], 1);
    int s5 = atomicAdd(&g_cur[cb.y], 1);
    int s6 = atomicAdd(&g_cur[cb.z], 1);
    int s7 = atomicAdd(&g_cur[cb.w], 1);
    g_csri[s0] = ra.x; g_csri[s1] = ra.y; g_csri[s2] = ra.z; g_csri[s3] = ra.w;
    g_csri[s4] = rb.x; g_csri[s5] = rb.y; g_csri[s6] = rb.z; g_csri[s7] = rb.w;
}

// ---------------- layer 1 fused: g_aggh = relu((A_hat@x)@W1 + b1) fp16 ----
__global__ void k_l1(const float* __restrict__ W1, const float* __restrict__ b1) {
    __shared__ __align__(16) float W1s[8 * 64];
    __shared__ __align__(16) float A[128 * 8];
    const int tid  = threadIdx.x;
    const int nloc = tid >> 1;
    const int half = tid & 1;
    const int n    = blockIdx.x * 128 + nloc;

    for (int i = tid; i < 512; i += 256) W1s[i] = W1[i];

    if (n < N_NODES) {
        const float4* xs4 = (const float4*)g_xs;
        int o0 = g_off[n], o1 = g_off[n + 1];
        float4 acc = xs4[(long)n * 2 + half];   // own scaled row
        int i = o0;
        for (; i + 2 <= o1; i += 2) {
            int r0 = g_csri[i], r1 = g_csri[i + 1];
            float4 v0 = xs4[(long)r0 * 2 + half];
            float4 v1 = xs4[(long)r1 * 2 + half];
            acc.x += v0.x + v1.x; acc.y += v0.y + v1.y;
            acc.z += v0.z + v1.z; acc.w += v0.w + v1.w;
        }
        if (i < o1) {
            float4 v0 = xs4[(long)g_csri[i] * 2 + half];
            acc.x += v0.x; acc.y += v0.y; acc.z += v0.z; acc.w += v0.w;
        }
        float dv = g_dinv[n];
        acc.x *= dv; acc.y *= dv; acc.z *= dv; acc.w *= dv;
        *(float4*)&A[nloc * 8 + half * 4] = acc;
    }
    __syncthreads();

    if (n < N_NODES) {
        float a[8];
        *(float4*)&a[0] = *(const float4*)&A[nloc * 8];
        *(float4*)&a[4] = *(const float4*)&A[nloc * 8 + 4];
        const int jc0 = half * 32;
        float4 acc[8];
#pragma unroll
        for (int g = 0; g < 8; g++) acc[g] = make_float4(0.f, 0.f, 0.f, 0.f);
#pragma unroll
        for (int k = 0; k < 8; k++) {
            float ak = a[k];
#pragma unroll
            for (int g = 0; g < 8; g++) {
                float4 w = *(const float4*)&W1s[k * 64 + jc0 + g * 4];
                acc[g].x = fmaf(ak, w.x, acc[g].x);
                acc[g].y = fmaf(ak, w.y, acc[g].y);
                acc[g].z = fmaf(ak, w.z, acc[g].z);
                acc[g].w = fmaf(ak, w.w, acc[g].w);
            }
        }
        // epilogue: h1 = relu(preact1 + b1) -> fp16
#pragma unroll
        for (int g = 0; g < 8; g++) {
            int j = jc0 + g * 4;
            float4 bb = *(const float4*)&b1[j];
            __half2 p0 = __floats2half2_rn(fmaxf(acc[g].x + bb.x, 0.f),
                                           fmaxf(acc[g].y + bb.y, 0.f));
            __half2 p1 = __floats2half2_rn(fmaxf(acc[g].z + bb.z, 0.f),
                                           fmaxf(acc[g].w + bb.w, 0.f));
            __half2 pair[2] = {p0, p1};
            *(uint2*)&g_aggh[(long)n * 64 + j] = *(uint2*)pair;
        }
    }
}

// ---------------- gather64_h: g_aggh = relu(dinv*(y[c]+sum y[r]) + b) fp16
// (used after layers 2,3 — feeds the next tensor-core GEMM)
__global__ void k_gather64_h(const float* __restrict__ bias) {
    int gwid = (blockIdx.x * blockDim.x + threadIdx.x) >> 5;
    int lane = threadIdx.x & 31;
    if (gwid >= N_NODES) return;
    const __half2* __restrict__ xw2 = (const __half2*)g_xwh;
    int o0 = g_off[gwid], o1 = g_off[gwid + 1];
    float2 acc = __half22float2(xw2[(long)gwid * 32 + lane]);  // own y row
    int i = o0;
    for (; i + 4 <= o1; i += 4) {
        int r0 = g_csri[i], r1 = g_csri[i + 1], r2 = g_csri[i + 2], r3 = g_csri[i + 3];
        float2 v0 = __half22float2(xw2[(long)r0 * 32 + lane]);
        float2 v1 = __half22float2(xw2[(long)r1 * 32 + lane]);
        float2 v2 = __half22float2(xw2[(long)r2 * 32 + lane]);
        float2 v3 = __half22float2(xw2[(long)r3 * 32 + lane]);
        acc.x += v0.x + v1.x; acc.y += v0.y + v1.y;
        acc.x += v2.x + v3.x; acc.y += v2.y + v3.y;
    }
    for (; i < o1; i++) {
        float2 v0 = __half22float2(xw2[(long)g_csri[i] * 32 + lane]);
        acc.x += v0.x; acc.y += v0.y;
    }
    float dv = g_dinv[gwid];
    float2 bb = *(const float2*)&bias[lane * 2];
    ((__half2*)g_aggh)[(long)gwid * 32 + lane] =
        __floats2half2_rn(fmaxf(acc.x * dv + bb.x, 0.f),
                          fmaxf(acc.y * dv + bb.y, 0.f));
}

// ---------------- gather64_f: g_agg = dinv*(y[c]+sum y[r]) fp32 (final) ---
__global__ void k_gather64_f() {
    int gwid = (blockIdx.x * blockDim.x + threadIdx.x) >> 5;
    int lane = threadIdx.x & 31;
    if (gwid >= N_NODES) return;
    const __half2* __restrict__ xw2 = (const __half2*)g_xwh;
    int o0 = g_off[gwid], o1 = g_off[gwid + 1];
    float2 acc = __half22float2(xw2[(long)gwid * 32 + lane]);
    int i = o0;
    for (; i + 4 <= o1; i += 4) {
        int r0 = g_csri[i], r1 = g_csri[i + 1], r2 = g_csri[i + 2], r3 = g_csri[i + 3];
        float2 v0 = __half22float2(xw2[(long)r0 * 32 + lane]);
        float2 v1 = __half22float2(xw2[(long)r1 * 32 + lane]);
        float2 v2 = __half22float2(xw2[(long)r2 * 32 + lane]);
        float2 v3 = __half22float2(xw2[(long)r3 * 32 + lane]);
        acc.x += v0.x + v1.x; acc.y += v0.y + v1.y;
        acc.x += v2.x + v3.x; acc.y += v2.y + v3.y;
    }
    for (; i < o1; i++) {
        float2 v0 = __half22float2(xw2[(long)g_csri[i] * 32 + lane]);
        acc.x += v0.x; acc.y += v0.y;
    }
    float dv = g_dinv[gwid];
    acc.x *= dv; acc.y *= dv;
    ((float2*)g_agg)[(long)gwid * 32 + lane] = acc;
}

// ---------------- GEMM K=64 tensor cores: g_xwh = dinv * (g_aggh @ W) -----
// A rows already activated fp16 (g_aggh). Staging = pure copy.
__global__ __launch_bounds__(256) void k_gemmT(const float* __restrict__ W) {
    __shared__ __align__(16) __half Sh[64 * 72];  // A fp16
    __shared__ __align__(16) __half Wh[64 * 72];  // W fp16
    __shared__ float Dv[64];
    const int tid  = threadIdx.x;
    const int base = blockIdx.x * 64;

    if (tid < 64) {
        int row = base + tid;
        Dv[tid] = (row < N_NODES) ? g_dinv[row] : 0.0f;
    }
    // stage A: copy fp16 rows (8B per thread-iter)
    for (int i = tid; i < 1024; i += 256) {
        int r = i >> 4, k4 = i & 15;        // k4 = uint2 index (4 halves)
        int row = base + r;
        uint2 v = make_uint2(0u, 0u);
        if (row < N_NODES) v = *(const uint2*)&g_aggh[(long)row * 64 + k4 * 4];
        *(uint2*)&Sh[r * 72 + k4 * 4] = v;
    }
    // stage W -> fp16
    for (int i = tid; i < 2048; i += 256) {
        int k = i >> 5, j2 = i & 31;
        float2 w = *(const float2*)&W[k * 64 + j2 * 2];
        ((__half2*)Wh)[k * 36 + j2] = __floats2half2_rn(w.x, w.y);
    }
    __syncthreads();

    const int warp = tid >> 5, lane = tid & 31;
    const int m_base = (warp >> 1) * 16;
    const int n_base = (warp & 1) * 32;
    const int lt   = lane & 7;
    const int tile = lane >> 3;

    float d[4][4];
#pragma unroll
    for (int nt = 0; nt < 4; nt++)
#pragma unroll
        for (int q = 0; q < 4; q++) d[nt][q] = 0.f;

#pragma unroll
    for (int kc = 0; kc < 4; kc++) {
        int arow = m_base + lt + ((tile & 1) ? 8 : 0);
        int acol = kc * 16 + ((tile & 2) ? 8 : 0);
        uint32_t a0, a1, a2, a3;
        {
            uint32_t addr = smem_u32(&Sh[arow * 72 + acol]);
            asm volatile("ldmatrix.sync.aligned.m8n8.x4.shared.b16 {%0,%1,%2,%3}, [%4];"
                         : "=r"(a0), "=r"(a1), "=r"(a2), "=r"(a3) : "r"(addr));
        }
#pragma unroll
        for (int g = 0; g < 2; g++) {
            int krow = kc * 16 + lt + ((tile & 1) ? 8 : 0);
            int bcol = n_base + g * 16 + ((tile & 2) ? 8 : 0);
            uint32_t b0, b1, b2, b3;
            uint32_t addr = smem_u32(&Wh[krow * 72 + bcol]);
            asm volatile("ldmatrix.sync.aligned.m8n8.x4.trans.shared.b16 {%0,%1,%2,%3}, [%4];"
                         : "=r"(b0), "=r"(b1), "=r"(b2), "=r"(b3) : "r"(addr));
            asm volatile("mma.sync.aligned.m16n8k16.row.col.f32.f16.f16.f32 "
                         "{%0,%1,%2,%3},{%4,%5,%6,%7},{%8,%9},{%0,%1,%2,%3};"
                         : "+f"(d[g*2][0]), "+f"(d[g*2][1]), "+f"(d[g*2][2]), "+f"(d[g*2][3])
                         : "r"(a0), "r"(a1), "r"(a2), "r"(a3), "r"(b0), "r"(b1));
            asm volatile("mma.sync.aligned.m16n8k16.row.col.f32.f16.f16.f32 "
                         "{%0,%1,%2,%3},{%4,%5,%6,%7},{%8,%9},{%0,%1,%2,%3};"
                         : "+f"(d[g*2+1][0]), "+f"(d[g*2+1][1]), "+f"(d[g*2+1][2]), "+f"(d[g*2+1][3])
                         : "r"(a0), "r"(a1), "r"(a2), "r"(a3), "r"(b2), "r"(b3));
        }
    }

    // epilogue: scale by dinv, fp16 store (y rows)
    const int group = lane >> 2, t4 = lane & 3;
    const int r0g = base + m_base + group;
    const int r1g = r0g + 8;
    const float dv0 = Dv[m_base + group];
    const float dv1 = Dv[m_base + group + 8];
#pragma unroll
    for (int nt = 0; nt < 4; nt++) {
        int ncol = n_base + nt * 8 + t4 * 2;
        if (r0g < N_NODES)
            *(__half2*)&g_xwh[(long)r0g * 64 + ncol] =
                __floats2half2_rn(d[nt][0] * dv0, d[nt][1] * dv0);
        if (r1g < N_NODES)
            *(__half2*)&g_xwh[(long)r1g * 64 + ncol] =
                __floats2half2_rn(d[nt][2] * dv1, d[nt][3] * dv1);
    }
}

// ---------------- pooling (sorted batch, run-length flush, 32-node chunks)
__global__ void k_pool(const float* __restrict__ b4, const int* __restrict__ batch) {
    int j = threadIdx.x & 63;
    int y = threadIdx.x >> 6;
    int start = blockIdx.x * 128 + y * 32;
    int end   = min(start + 32, N_NODES);
    if (start >= end) return;

    float bj = b4[j];
    int   curg = batch[start];
    float mx = 0.f, sm = 0.f;
    int   cnt = 0;

    for (int n = start; n < end; n++) {
        int g = batch[n];
        if (g != curg) {
            atomicMax((int*)&g_gmax[curg * 64 + j], __float_as_int(mx));
            atomicAdd(&g_gsum[curg * 64 + j], sm);
            if (j == 0) atomicAdd(&g_gcnt[curg], (float)cnt);
            curg = g; mx = 0.f; sm = 0.f; cnt = 0;
        }
        float v = fmaxf(g_agg[(long)n * 64 + j] + bj, 0.0f);
        mx = fmaxf(mx, v);
        sm += v;
        cnt++;
    }
    atomicMax((int*)&g_gmax[curg * 64 + j], __float_as_int(mx));
    atomicAdd(&g_gsum[curg * 64 + j], sm);
    if (j == 0) atomicAdd(&g_gcnt[curg], (float)cnt);
}

// ---------------- head ----------------------------------------------------
__global__ void k_head(const float* __restrict__ Wo, const float* __restrict__ bo,
                       float* __restrict__ out, int write_hg) {
    int g = blockIdx.x;
    int j = threadIdx.x;  // 0..127
    float cnt = fmaxf(g_gcnt[g], 1.0f);
    float val = (j < 64) ? g_gmax[g * 64 + j] : g_gsum[g * 64 + (j - 64)] / cnt;
    if (write_hg) out[N_GRAPHS + (long)g * 128 + j] = val;

    float p = val * Wo[j];
#pragma unroll
    for (int off = 16; off > 0; off >>= 1)
        p += __shfl_down_sync(0xffffffff, p, off);

    __shared__ float red[4];
    if ((j & 31) == 0) red[j >> 5] = p;
    __syncthreads();
    if (j == 0) out[g] = red[0] + red[1] + red[2] + red[3] + bo[0];
}

// ---------------- launch ---------------------------------------------------
extern "C" void kernel_launch(void* const* d_in, const int* in_sizes, int n_in,
                              void* d_out, int out_size) {
    const float* x     = (const float*)d_in[0];
    const int*   ei    = (const int*)  d_in[1];   // [2, E]
    const int*   batch = (const int*)  d_in[2];
    const float* W1 = (const float*)d_in[3];  const float* b1 = (const float*)d_in[4];
    const float* W2 = (const float*)d_in[5];  const float* b2 = (const float*)d_in[6];
    const float* W3 = (const float*)d_in[7];  const float* b3 = (const float*)d_in[8];
    const float* W4 = (const float*)d_in[9];  const float* b4 = (const float*)d_in[10];
    const float* Wo = (const float*)d_in[11]; const float* bo = (const float*)d_in[12];

    const int* rows = ei;            // source
    const int* cols = ei + N_EDGES;  // target

    float* out = (float*)d_out;
    int write_hg = (out_size >= N_GRAPHS + N_GRAPHS * 2 * HDIM) ? 1 : 0;

    const int NB_N  = (N_NODES + 255) / 256;
    const int NB_E8 = (N_EDGES / 8 + 255) / 256;

    // CSR build (g_deg arrives zeroed from previous call / load-time init)
    k_deg_count<<<NB_E8, 256>>>(cols);
    k_scan1    <<<SCAN_NB, SCAN_B>>>();
    k_scan3    <<<NB_N, 256>>>(x);
    k_fill     <<<NB_E8, 256>>>(rows, cols);

    const int L1_BLKS  = (N_NODES + 127) / 128;          // 782
    const int GT_BLKS  = (N_NODES + 63) / 64;            // 1563
    const int G64_BLKS = (N_NODES * 32 + 255) / 256;     // 12500

    // layer 1: fused 8-dim gather + GEMM + bias/relu -> g_aggh (h1, fp16)
    k_l1<<<L1_BLKS, 256>>>(W1, b1);
    // layers 2..4: y = dinv*(h @ W) fp16, gather -> h_{l+1} (or preact4 fp32)
    k_gemmT<<<GT_BLKS, 256>>>(W2);
    k_gather64_h<<<G64_BLKS, 256>>>(b2);           // g_aggh = h2
    k_gemmT<<<GT_BLKS, 256>>>(W3);
    k_gather64_h<<<G64_BLKS, 256>>>(b3);           // g_aggh = h3
    k_gemmT<<<GT_BLKS, 256>>>(W4);
    k_gather64_f<<<G64_BLKS, 256>>>();             // g_agg = preact4 (fp32)

    // pooling + head (relu(+b4) fused in pool)
    k_pool<<<(N_NODES + 127) / 128, 256>>>(b4, batch);
    k_head<<<N_GRAPHS, 128>>>(Wo, bo, out, write_hg);
}